// round 1
// baseline (speedup 1.0000x reference)
#include <cuda_runtime.h>
#include <cstdint>
#include <math.h>

// Problem constants (fixed shapes from reference setup_inputs)
#define D      4096
#define E      512
#define BROWS  8192
#define NQ     (1ull*BROWS*D)   // 33554432 quantized elements
#define NENC   (1ull*BROWS*E)   // 4194304 encoding elements

// Output layout assumption (tuple flattened & concatenated):
// [0]                    : loss
// [1 .. 1+NQ)            : quantized_st
// [1+NQ]                 : perplexity
// [2+NQ .. 2+NQ+NENC)    : encodings
#define OUT_Q_OFF    1ull
#define OUT_PERP_OFF (1ull + NQ)
#define OUT_ENC_OFF  (2ull + NQ)

// Scratch (device globals; no allocations allowed)
__device__ float              g_cnorm[E];
__device__ unsigned long long g_best[BROWS];
__device__ int                g_counts[E];
__device__ double             g_loss;

// Monotone float->uint mapping, then pack (dist, idx) so u64 atomicMin gives
// argmin with ties resolved to the LOWEST index (matches jnp.argmin).
__device__ __forceinline__ unsigned long long make_key(float d, int idx) {
    unsigned int u = __float_as_uint(d);
    u = (u & 0x80000000u) ? ~u : (u | 0x80000000u);
    return ((unsigned long long)u << 32) | (unsigned int)idx;
}

// ---------------- init ----------------
__global__ void init_kernel() {
    int i = blockIdx.x * blockDim.x + threadIdx.x;
    if (i < BROWS) g_best[i] = 0xFFFFFFFFFFFFFFFFull;
    if (i < E)     g_counts[i] = 0;
    if (i == 0)    g_loss = 0.0;
}

// ---------------- codebook norms ----------------
__global__ void cnorm_kernel(const float* __restrict__ C) {
    int e = blockIdx.x;
    const float4* row = (const float4*)(C + (size_t)e * D);
    float s = 0.f;
    for (int i = threadIdx.x; i < D / 4; i += blockDim.x) {
        float4 v = row[i];
        s += v.x * v.x + v.y * v.y + v.z * v.z + v.w * v.w;
    }
    for (int o = 16; o; o >>= 1) s += __shfl_down_sync(0xffffffffu, s, o);
    __shared__ float ws[4];
    if ((threadIdx.x & 31) == 0) ws[threadIdx.x >> 5] = s;
    __syncthreads();
    if (threadIdx.x == 0) g_cnorm[e] = ws[0] + ws[1] + ws[2] + ws[3];
}

// ---------------- fused fp32 GEMM + argmin ----------------
// Computes dot = X @ C^T tile-wise; epilogue folds d = ||c||^2 - 2*dot into a
// per-row running argmin via packed u64 atomicMin. (||x||^2 dropped: constant
// per row, does not affect argmin.)
#define BM 128
#define BN 128
#define BK 16

__global__ __launch_bounds__(256, 2)
void gemm_argmin_kernel(const float* __restrict__ X, const float* __restrict__ C) {
    __shared__ float Xs[BK][BM];
    __shared__ float Cs[BK][BN];
    __shared__ unsigned long long rowbest[BM];

    const int tid = threadIdx.x;
    const int tx = tid & 15;       // 0..15 -> 8 cols each
    const int ty = tid >> 4;       // 0..15 -> 8 rows each
    const int rowBase = blockIdx.y * BM;
    const int colBase = blockIdx.x * BN;

    float acc[8][8];
#pragma unroll
    for (int i = 0; i < 8; i++)
#pragma unroll
        for (int j = 0; j < 8; j++) acc[i][j] = 0.f;

    const float* Xg = X + (size_t)rowBase * D;
    const float* Cg = C + (size_t)colBase * D;

    float4 px[2], pc[2];
    // prefetch tile 0
#pragma unroll
    for (int i = 0; i < 2; i++) {
        int idx = tid + i * 256;
        int m = idx >> 2, kc = idx & 3;
        px[i] = *(const float4*)(Xg + (size_t)m * D + kc * 4);
        pc[i] = *(const float4*)(Cg + (size_t)m * D + kc * 4);
    }

    const int NT = D / BK;  // 256
    for (int t = 0; t < NT; t++) {
        // store current tile to smem (transposed: Xs[k][m])
#pragma unroll
        for (int i = 0; i < 2; i++) {
            int idx = tid + i * 256;
            int m = idx >> 2, kc = idx & 3;
            Xs[kc * 4 + 0][m] = px[i].x;
            Xs[kc * 4 + 1][m] = px[i].y;
            Xs[kc * 4 + 2][m] = px[i].z;
            Xs[kc * 4 + 3][m] = px[i].w;
            Cs[kc * 4 + 0][m] = pc[i].x;
            Cs[kc * 4 + 1][m] = pc[i].y;
            Cs[kc * 4 + 2][m] = pc[i].z;
            Cs[kc * 4 + 3][m] = pc[i].w;
        }
        __syncthreads();

        // prefetch next tile (overlaps with compute)
        if (t + 1 < NT) {
            int k0 = (t + 1) * BK;
#pragma unroll
            for (int i = 0; i < 2; i++) {
                int idx = tid + i * 256;
                int m = idx >> 2, kc = idx & 3;
                px[i] = *(const float4*)(Xg + (size_t)m * D + k0 + kc * 4);
                pc[i] = *(const float4*)(Cg + (size_t)m * D + k0 + kc * 4);
            }
        }

#pragma unroll
        for (int kk = 0; kk < BK; kk++) {
            float4 a0 = *(const float4*)&Xs[kk][ty * 8];
            float4 a1 = *(const float4*)&Xs[kk][ty * 8 + 4];
            float4 b0 = *(const float4*)&Cs[kk][tx * 8];
            float4 b1 = *(const float4*)&Cs[kk][tx * 8 + 4];
            float a[8] = {a0.x, a0.y, a0.z, a0.w, a1.x, a1.y, a1.z, a1.w};
            float b[8] = {b0.x, b0.y, b0.z, b0.w, b1.x, b1.y, b1.z, b1.w};
#pragma unroll
            for (int i = 0; i < 8; i++)
#pragma unroll
                for (int j = 0; j < 8; j++)
                    acc[i][j] = fmaf(a[i], b[j], acc[i][j]);
        }
        __syncthreads();
    }

    // ---- epilogue: per-row argmin within block, then global atomicMin ----
    for (int i = tid; i < BM; i += 256) rowbest[i] = 0xFFFFFFFFFFFFFFFFull;
    __syncthreads();

#pragma unroll
    for (int i = 0; i < 8; i++) {
        int r = ty * 8 + i;
        unsigned long long best = 0xFFFFFFFFFFFFFFFFull;
#pragma unroll
        for (int j = 0; j < 8; j++) {
            int gcol = colBase + tx * 8 + j;
            float dist = g_cnorm[gcol] - 2.0f * acc[i][j];
            unsigned long long k = make_key(dist, gcol);
            best = (k < best) ? k : best;
        }
        atomicMin(&rowbest[r], best);
    }
    __syncthreads();
    for (int i = tid; i < BM; i += 256)
        atomicMin(&g_best[rowBase + i], rowbest[i]);
}

// ---------------- finalize: gather, ST output, loss, counts, encodings ----------------
__global__ void finalize_kernel(const float* __restrict__ X,
                                const float* __restrict__ C,
                                float* __restrict__ out) {
    const int row = blockIdx.x;
    const int tid = threadIdx.x;  // 128 threads
    const int idx = (int)(g_best[row] & 0xffffffffull);

    const float4* x4 = (const float4*)(X + (size_t)row * D);
    const float4* c4 = (const float4*)(C + (size_t)idx * D);
    float* qout = out + OUT_Q_OFF + (size_t)row * D;  // offset 1: not 16B aligned -> scalar stores

    float s = 0.f;
#pragma unroll
    for (int i = tid; i < D / 4; i += 128) {  // 8 iters
        float4 xv = x4[i];
        float4 cv = c4[i];
        // straight-through: x + (q - x), computed exactly as reference does
        float d0 = cv.x - xv.x, d1 = cv.y - xv.y, d2 = cv.z - xv.z, d3 = cv.w - xv.w;
        qout[i * 4 + 0] = xv.x + d0;
        qout[i * 4 + 1] = xv.y + d1;
        qout[i * 4 + 2] = xv.z + d2;
        qout[i * 4 + 3] = xv.w + d3;
        s += d0 * d0 + d1 * d1 + d2 * d2 + d3 * d3;
    }
    for (int o = 16; o; o >>= 1) s += __shfl_down_sync(0xffffffffu, s, o);
    __shared__ float ws[4];
    if ((tid & 31) == 0) ws[tid >> 5] = s;
    __syncthreads();
    if (tid == 0) {
        atomicAdd(&g_loss, (double)(ws[0] + ws[1] + ws[2] + ws[3]));
        atomicAdd(&g_counts[idx], 1);
    }

    // encodings row (one-hot). Region start offset 2+NQ is misaligned for
    // float4 -> scalar stores.
    float* enc = out + OUT_ENC_OFF + (size_t)row * E;
#pragma unroll
    for (int j = tid; j < E; j += 128)
        enc[j] = (j == idx) ? 1.0f : 0.0f;
}

// ---------------- scalars: loss + perplexity ----------------
__global__ void scalars_kernel(float* __restrict__ out) {
    const int e = threadIdx.x;  // 512 threads
    float p = (float)g_counts[e] / (float)BROWS;
    float term = p * logf(p + 1e-10f);
    for (int o = 16; o; o >>= 1) term += __shfl_down_sync(0xffffffffu, term, o);
    __shared__ float ws[16];
    if ((e & 31) == 0) ws[e >> 5] = term;
    __syncthreads();
    if (e == 0) {
        float H = 0.f;
        for (int w = 0; w < 16; w++) H += ws[w];
        out[0] = (float)(1.25 * (g_loss / (double)NQ));  // q_loss + 0.25*e_loss
        out[OUT_PERP_OFF] = expf(-H);
    }
}

// ---------------- launch ----------------
extern "C" void kernel_launch(void* const* d_in, const int* in_sizes, int n_in,
                              void* d_out, int out_size) {
    const float* X = (const float*)d_in[0];
    const float* C = (const float*)d_in[1];
    // Defensive: if metadata order is (codebook, inputs), swap.
    if (n_in >= 2 && in_sizes[0] == E * D && in_sizes[1] == BROWS * D) {
        const float* t = X; X = C; C = t;
    }
    float* out = (float*)d_out;

    init_kernel<<<(BROWS + 255) / 256, 256>>>();
    cnorm_kernel<<<E, 128>>>(C);
    dim3 grid(E / BN, BROWS / BM);  // (4, 64)
    gemm_argmin_kernel<<<grid, 256>>>(X, C);
    finalize_kernel<<<BROWS, 128>>>(X, C, out);
    scalars_kernel<<<1, E>>>(out);
}

// round 4
// speedup vs baseline: 5.1267x; 5.1267x over previous
#include <cuda_runtime.h>
#include <cuda_bf16.h>
#include <cstdint>
#include <math.h>

#define D      4096
#define E      512
#define BROWS  8192
#define NQ     (1ull*BROWS*D)
#define NENC   (1ull*BROWS*E)

#define OUT_Q_OFF    1ull
#define OUT_PERP_OFF (1ull + NQ)
#define OUT_ENC_OFF  (2ull + NQ)

#define MARGIN 4.0f

// ---------------- device scratch ----------------
__device__ float          g_cnorm[E];
__device__ float          g_dist[(size_t)BROWS * E];   // 16 MB approx distances
__device__ __nv_bfloat16  g_Cb[(size_t)E * D];         // 4 MB bf16 codebook
__device__ int            g_idx[BROWS];
__device__ int            g_counts[E];
__device__ double         g_loss;

#define SWZ128(off) ((off) ^ (((off) >> 3) & 0x70))

__device__ __forceinline__ uint32_t smem_to_u32(const void* p) {
    uint32_t a;
    asm("{ .reg .u64 t; cvta.to.shared.u64 t, %1; cvt.u32.u64 %0, t; }" : "=r"(a) : "l"(p));
    return a;
}

// key packing: monotone float -> u32, argmin with ties -> lowest index
__device__ __forceinline__ unsigned long long make_key(float d, int idx) {
    unsigned int u = __float_as_uint(d);
    u = (u & 0x80000000u) ? ~u : (u | 0x80000000u);
    return ((unsigned long long)u << 32) | (unsigned int)idx;
}
__device__ __forceinline__ float key_to_float(unsigned long long k) {
    unsigned int u = (unsigned int)(k >> 32);
    u = (u & 0x80000000u) ? (u ^ 0x80000000u) : ~u;
    return __uint_as_float(u);
}

// ---------------- init ----------------
__global__ void init_kernel() {
    int i = blockIdx.x * blockDim.x + threadIdx.x;
    if (i < E)  g_counts[i] = 0;
    if (i == 0) g_loss = 0.0;
}

// ---------------- codebook: bf16 convert ----------------
__global__ void convC_kernel(const float* __restrict__ C) {
    size_t i = (size_t)blockIdx.x * blockDim.x + threadIdx.x;   // one float4
    float4 v = ((const float4*)C)[i];
    __nv_bfloat162 lo = __floats2bfloat162_rn(v.x, v.y);
    __nv_bfloat162 hi = __floats2bfloat162_rn(v.z, v.w);
    uint2 p; p.x = *(uint32_t*)&lo; p.y = *(uint32_t*)&hi;
    ((uint2*)g_Cb)[i] = p;
}

// ---------------- codebook norms (exact fp32) ----------------
__global__ void cnorm_kernel(const float* __restrict__ C) {
    int e = blockIdx.x;
    const float4* row = (const float4*)(C + (size_t)e * D);
    float s = 0.f;
    for (int i = threadIdx.x; i < D / 4; i += blockDim.x) {
        float4 v = row[i];
        s += v.x * v.x + v.y * v.y + v.z * v.z + v.w * v.w;
    }
    for (int o = 16; o; o >>= 1) s += __shfl_down_sync(0xffffffffu, s, o);
    __shared__ float ws[4];
    if ((threadIdx.x & 31) == 0) ws[threadIdx.x >> 5] = s;
    __syncthreads();
    if (threadIdx.x == 0) g_cnorm[e] = ws[0] + ws[1] + ws[2] + ws[3];
}

// ---------------- mma.sync bf16 GEMM: approx distances ----------------
// CTA 256 thr = 8 warps (2M x 4N), tile M=128 x N=256, warp tile 64x64.
// K chunk = 64 bf16 (128B SW128 rows), double-buffered smem.
#define TM 128
#define TN 256
#define CH 64
#define NCHUNK (D / CH)          // 64
#define A_BYTES 16384            // 128 rows * 128B
#define B_BYTES 32768            // 256 rows * 128B
#define GEMM_SMEM (2*A_BYTES + 2*B_BYTES)   // 98304

__global__ __launch_bounds__(256, 1)
void gemm_mma_kernel(const float* __restrict__ X) {
    extern __shared__ __align__(1024) char smem[];
    const int tid  = threadIdx.x;
    const int lane = tid & 31;
    const int wid  = tid >> 5;
    const int warpM = wid >> 2;   // 0..1
    const int warpN = wid & 3;    // 0..3
    const int rowBase = blockIdx.y * TM;
    const int colBase = blockIdx.x * TN;

    uint32_t sbA[2] = { smem_to_u32(smem),           smem_to_u32(smem) + A_BYTES };
    uint32_t sbB[2] = { smem_to_u32(smem) + 2*A_BYTES, smem_to_u32(smem) + 2*A_BYTES + B_BYTES };
    char* pA[2] = { smem, smem + A_BYTES };

    const float* Xg0 = X + (size_t)rowBase * D;
    const __nv_bfloat16* Cg0 = g_Cb + (size_t)colBase * D;

    // load coords (u = tid + i*256)
    const int ar  = tid >> 4, ac4  = tid & 15;   // A: 16 thr/row, float4 each
    const int br  = tid >> 3, bc16 = tid & 7;    // B: 8 thr/row, 16B each

    float acc[4][8][4];
#pragma unroll
    for (int mi = 0; mi < 4; mi++)
#pragma unroll
        for (int ni = 0; ni < 8; ni++)
#pragma unroll
            for (int r = 0; r < 4; r++) acc[mi][ni][r] = 0.f;

    float4 av[8];

    // ---- preload chunk 0 ----
#pragma unroll
    for (int i = 0; i < 8; i++) {
        int r = br + i * 32;
        uint32_t dst = sbB[0] + SWZ128((uint32_t)(r * 128 + bc16 * 16));
        const __nv_bfloat16* src = Cg0 + (size_t)r * D + bc16 * 8;
        asm volatile("cp.async.cg.shared.global [%0], [%1], 16;" :: "r"(dst), "l"(src));
    }
    asm volatile("cp.async.commit_group;" ::: "memory");
#pragma unroll
    for (int i = 0; i < 8; i++)
        av[i] = *(const float4*)(Xg0 + (size_t)(ar + i * 16) * D + ac4 * 4);

    for (int kt = 0; kt < NCHUNK; kt++) {
        const int buf = kt & 1;

        // STS A (convert fp32 -> bf16, SW128)
#pragma unroll
        for (int i = 0; i < 8; i++) {
            int r = ar + i * 16;
            __nv_bfloat162 lo = __floats2bfloat162_rn(av[i].x, av[i].y);
            __nv_bfloat162 hi = __floats2bfloat162_rn(av[i].z, av[i].w);
            uint2 p; p.x = *(uint32_t*)&lo; p.y = *(uint32_t*)&hi;
            *(uint2*)(pA[buf] + SWZ128((uint32_t)(r * 128 + ac4 * 8))) = p;
        }
        asm volatile("cp.async.wait_group 0;" ::: "memory");
        __syncthreads();

        // prefetch next chunk (overlaps MMA below)
        if (kt + 1 < NCHUNK) {
            const int nb = buf ^ 1;
            const int k0 = (kt + 1) * CH;
#pragma unroll
            for (int i = 0; i < 8; i++) {
                int r = br + i * 32;
                uint32_t dst = sbB[nb] + SWZ128((uint32_t)(r * 128 + bc16 * 16));
                const __nv_bfloat16* src = Cg0 + (size_t)r * D + k0 + bc16 * 8;
                asm volatile("cp.async.cg.shared.global [%0], [%1], 16;" :: "r"(dst), "l"(src));
            }
            asm volatile("cp.async.commit_group;" ::: "memory");
#pragma unroll
            for (int i = 0; i < 8; i++)
                av[i] = *(const float4*)(Xg0 + (size_t)(ar + i * 16) * D + k0 + ac4 * 4);
        }

        // ---- compute: 4 k16 steps ----
        const uint32_t aB = sbA[buf], bB = sbB[buf];
        const int a_r = lane & 15;
        const int a_c = (lane >> 4) * 16;
        const int b_n = ((lane >> 4) << 3) + (lane & 7);
        const int b_c = ((lane >> 3) & 1) * 16;
#pragma unroll
        for (int kk = 0; kk < 4; kk++) {
            uint32_t af[4][4], bfr[4][4];
#pragma unroll
            for (int mi = 0; mi < 4; mi++) {
                uint32_t addr = aB + SWZ128((uint32_t)((warpM * 64 + mi * 16 + a_r) * 128 + kk * 32 + a_c));
                asm volatile("ldmatrix.sync.aligned.m8n8.x4.shared.b16 {%0,%1,%2,%3}, [%4];"
                    : "=r"(af[mi][0]), "=r"(af[mi][1]), "=r"(af[mi][2]), "=r"(af[mi][3]) : "r"(addr));
            }
#pragma unroll
            for (int ng = 0; ng < 4; ng++) {
                uint32_t addr = bB + SWZ128((uint32_t)((warpN * 64 + ng * 16 + b_n) * 128 + kk * 32 + b_c));
                asm volatile("ldmatrix.sync.aligned.m8n8.x4.shared.b16 {%0,%1,%2,%3}, [%4];"
                    : "=r"(bfr[ng][0]), "=r"(bfr[ng][1]), "=r"(bfr[ng][2]), "=r"(bfr[ng][3]) : "r"(addr));
            }
#pragma unroll
            for (int mi = 0; mi < 4; mi++)
#pragma unroll
                for (int ng = 0; ng < 4; ng++) {
                    asm volatile("mma.sync.aligned.m16n8k16.row.col.f32.bf16.bf16.f32 "
                        "{%0,%1,%2,%3}, {%4,%5,%6,%7}, {%8,%9}, {%0,%1,%2,%3};"
                        : "+f"(acc[mi][2*ng][0]), "+f"(acc[mi][2*ng][1]),
                          "+f"(acc[mi][2*ng][2]), "+f"(acc[mi][2*ng][3])
                        : "r"(af[mi][0]), "r"(af[mi][1]), "r"(af[mi][2]), "r"(af[mi][3]),
                          "r"(bfr[ng][0]), "r"(bfr[ng][1]));
                    asm volatile("mma.sync.aligned.m16n8k16.row.col.f32.bf16.bf16.f32 "
                        "{%0,%1,%2,%3}, {%4,%5,%6,%7}, {%8,%9}, {%0,%1,%2,%3};"
                        : "+f"(acc[mi][2*ng+1][0]), "+f"(acc[mi][2*ng+1][1]),
                          "+f"(acc[mi][2*ng+1][2]), "+f"(acc[mi][2*ng+1][3])
                        : "r"(af[mi][0]), "r"(af[mi][1]), "r"(af[mi][2]), "r"(af[mi][3]),
                          "r"(bfr[ng][2]), "r"(bfr[ng][3]));
                }
        }
    }

    // ---- epilogue: dist = cnorm - 2*dot, direct stores ----
    const int g = lane >> 2, t = lane & 3;
#pragma unroll
    for (int mi = 0; mi < 4; mi++) {
        int row0 = rowBase + warpM * 64 + mi * 16 + g;
#pragma unroll
        for (int ni = 0; ni < 8; ni++) {
            int col = colBase + warpN * 64 + ni * 8 + 2 * t;
            float cn0 = g_cnorm[col], cn1 = g_cnorm[col + 1];
            float2 v0 = make_float2(cn0 - 2.f * acc[mi][ni][0], cn1 - 2.f * acc[mi][ni][1]);
            float2 v1 = make_float2(cn0 - 2.f * acc[mi][ni][2], cn1 - 2.f * acc[mi][ni][3]);
            *(float2*)(g_dist + (size_t)row0 * E + col) = v0;
            *(float2*)(g_dist + (size_t)(row0 + 8) * E + col) = v1;
        }
    }
}

// ---------------- rescue: exact argmin ----------------
__global__ __launch_bounds__(128)
void rescue_kernel(const float* __restrict__ X, const float* __restrict__ C) {
    const int row = blockIdx.x;
    const int tid = threadIdx.x;
    const int lane = tid & 31, wid = tid >> 5;
    const float* drow = g_dist + (size_t)row * E;

    float dval[4];
    int   dcol[4];
    unsigned long long k = 0xFFFFFFFFFFFFFFFFull;
#pragma unroll
    for (int i = 0; i < 4; i++) {
        int c = tid + i * 128;
        dval[i] = drow[c]; dcol[i] = c;
        unsigned long long kk = make_key(dval[i], c);
        k = (kk < k) ? kk : k;
    }
    for (int o = 16; o; o >>= 1) {
        unsigned long long kk = __shfl_down_sync(0xffffffffu, k, o);
        k = (kk < k) ? kk : k;
    }
    __shared__ unsigned long long wk[4];
    __shared__ unsigned long long bestK;
    __shared__ int cnt;
    __shared__ int cand[64];
    __shared__ float ws[4];
    __shared__ float xnorm_s;
    if (lane == 0) wk[wid] = k;
    if (tid == 0) cnt = 0;
    __syncthreads();
    if (tid == 0) {
        unsigned long long b = wk[0];
        if (wk[1] < b) b = wk[1];
        if (wk[2] < b) b = wk[2];
        if (wk[3] < b) b = wk[3];
        bestK = b;
    }
    __syncthreads();
    float bd = key_to_float(bestK);
#pragma unroll
    for (int i = 0; i < 4; i++) {
        if (dval[i] <= bd + MARGIN) {
            int p = atomicAdd(&cnt, 1);
            if (p < 64) cand[p] = dcol[i];
        }
    }
    __syncthreads();
    int n = cnt;
    if (n == 1) {
        if (tid == 0) g_idx[row] = (int)(bestK & 0xffffffffull);
        return;
    }
    if (n > 64) n = 64;

    const float4* x4 = (const float4*)(X + (size_t)row * D);
    float xs = 0.f;
#pragma unroll
    for (int i = tid; i < D / 4; i += 128) {
        float4 xv = x4[i];
        xs += xv.x * xv.x + xv.y * xv.y + xv.z * xv.z + xv.w * xv.w;
    }
    for (int o = 16; o; o >>= 1) xs += __shfl_down_sync(0xffffffffu, xs, o);
    if (lane == 0) ws[wid] = xs;
    __syncthreads();
    if (tid == 0) xnorm_s = ws[0] + ws[1] + ws[2] + ws[3];

    unsigned long long bestE = 0xFFFFFFFFFFFFFFFFull;
    for (int t = 0; t < n; t++) {
        int cidx = cand[t];
        const float4* c4 = (const float4*)(C + (size_t)cidx * D);
        float s = 0.f;
#pragma unroll
        for (int i = tid; i < D / 4; i += 128) {
            float4 xv = x4[i];
            float4 cv = c4[i];
            s += xv.x * cv.x + xv.y * cv.y + xv.z * cv.z + xv.w * cv.w;
        }
        for (int o = 16; o; o >>= 1) s += __shfl_down_sync(0xffffffffu, s, o);
        __syncthreads();
        if (lane == 0) ws[wid] = s;
        __syncthreads();
        if (tid == 0) {
            float dot = ws[0] + ws[1] + ws[2] + ws[3];
            float dist = (xnorm_s + g_cnorm[cidx]) - 2.f * dot;
            unsigned long long kk = make_key(dist, cidx);
            bestE = (kk < bestE) ? kk : bestE;
        }
    }
    if (tid == 0) g_idx[row] = (int)(bestE & 0xffffffffull);
}

// ---------------- finalize: gather, ST, loss, counts, encodings ----------------
__global__ __launch_bounds__(128)
void finalize_kernel(const float* __restrict__ X,
                     const float* __restrict__ C,
                     float* __restrict__ out) {
    __shared__ float q[D];   // 16KB staging for aligned stores
    __shared__ float ws[4];
    const int row = blockIdx.x;
    const int tid = threadIdx.x;
    const int idx = g_idx[row];

    const float4* x4 = (const float4*)(X + (size_t)row * D);
    const float4* c4 = (const float4*)(C + (size_t)idx * D);

    float s = 0.f;
#pragma unroll
    for (int i = tid; i < D / 4; i += 128) {
        float4 xv = x4[i];
        float4 cv = c4[i];
        float d0 = cv.x - xv.x, d1 = cv.y - xv.y, d2 = cv.z - xv.z, d3 = cv.w - xv.w;
        q[i * 4 + 0] = xv.x + d0;
        q[i * 4 + 1] = xv.y + d1;
        q[i * 4 + 2] = xv.z + d2;
        q[i * 4 + 3] = xv.w + d3;
        s += d0 * d0 + d1 * d1 + d2 * d2 + d3 * d3;
    }
    for (int o = 16; o; o >>= 1) s += __shfl_down_sync(0xffffffffu, s, o);
    if ((tid & 31) == 0) ws[tid >> 5] = s;
    __syncthreads();
    if (tid == 0) {
        atomicAdd(&g_loss, (double)(ws[0] + ws[1] + ws[2] + ws[3]));
        atomicAdd(&g_counts[idx], 1);
    }

    // quantized_st: base offset 1 -> first aligned16 at k=3
    float* qo = out + OUT_Q_OFF + (size_t)row * D;
    if (tid == 0) { qo[0] = q[0]; qo[1] = q[1]; qo[2] = q[2]; qo[D - 1] = q[D - 1]; }
#pragma unroll
    for (int i = tid; i < 1023; i += 128) {
        int k = 3 + i * 4;
        *(float4*)(qo + k) = make_float4(q[k], q[k + 1], q[k + 2], q[k + 3]);
    }

    // encodings: base%4==2 -> scalars at edges, float4 middle
    float* enc = out + OUT_ENC_OFF + (size_t)row * E;
    if (tid == 0) {
        enc[0]   = (idx == 0)   ? 1.f : 0.f;
        enc[1]   = (idx == 1)   ? 1.f : 0.f;
        enc[510] = (idx == 510) ? 1.f : 0.f;
        enc[511] = (idx == 511) ? 1.f : 0.f;
    }
    for (int i = tid; i < 127; i += 128) {
        int k = 2 + i * 4;
        float4 v = make_float4((idx == k) ? 1.f : 0.f, (idx == k + 1) ? 1.f : 0.f,
                               (idx == k + 2) ? 1.f : 0.f, (idx == k + 3) ? 1.f : 0.f);
        *(float4*)(enc + k) = v;
    }
}

// ---------------- scalars ----------------
__global__ void scalars_kernel(float* __restrict__ out) {
    const int e = threadIdx.x;  // 512 threads
    float p = (float)g_counts[e] / (float)BROWS;
    float term = p * logf(p + 1e-10f);
    for (int o = 16; o; o >>= 1) term += __shfl_down_sync(0xffffffffu, term, o);
    __shared__ float ws[16];
    if ((e & 31) == 0) ws[e >> 5] = term;
    __syncthreads();
    if (e == 0) {
        float H = 0.f;
        for (int w = 0; w < 16; w++) H += ws[w];
        out[0] = (float)(1.25 * (g_loss / (double)NQ));
        out[OUT_PERP_OFF] = expf(-H);
    }
}

// ---------------- launch ----------------
extern "C" void kernel_launch(void* const* d_in, const int* in_sizes, int n_in,
                              void* d_out, int out_size) {
    const float* X = (const float*)d_in[0];
    const float* C = (const float*)d_in[1];
    if (n_in >= 2 && in_sizes[0] == E * D && in_sizes[1] == BROWS * D) {
        const float* t = X; X = C; C = t;
    }
    float* out = (float*)d_out;

    static bool attr_done = false;
    if (!attr_done) {
        cudaFuncSetAttribute(gemm_mma_kernel,
                             cudaFuncAttributeMaxDynamicSharedMemorySize, GEMM_SMEM);
        attr_done = true;
    }

    init_kernel<<<2, 256>>>();
    convC_kernel<<<(E * D / 4) / 256, 256>>>(C);
    cnorm_kernel<<<E, 128>>>(C);
    dim3 grid(E / TN, BROWS / TM);   // (2, 64)
    gemm_mma_kernel<<<grid, 256, GEMM_SMEM>>>(X);
    rescue_kernel<<<BROWS, 128>>>(X, C);
    finalize_kernel<<<BROWS, 128>>>(X, C, out);
    scalars_kernel<<<1, E>>>(out);
}